// round 11
// baseline (speedup 1.0000x reference)
#include <cuda_runtime.h>
#include <cstdint>

#define Dm 512
#define Sq 512
#define Bz 4
#define Hh 8
#define FF 2048
#define NL 6
#define TOK (Bz*Sq)        // 2048 tokens
#define NEGV (-1000000000.0f)

// ---------------- scratch (no allocations allowed) ----------------
__device__ float g_Q  [TOK*Dm];
__device__ float g_K  [TOK*Dm];
__device__ float g_V  [TOK*Dm];
__device__ float g_Ctx[TOK*Dm];
__device__ float g_Tmp[TOK*Dm];
__device__ float g_Ffn[TOK*FF];
__device__ float g_Enc[TOK*Dm];
__device__ float g_Dec[TOK*Dm];

// ---------------- PTX helpers ----------------
__device__ __forceinline__ uint32_t smem_u32(const void* p) {
    return (uint32_t)__cvta_generic_to_shared(p);
}
__device__ __forceinline__ void cpasync16(uint32_t dst, const void* src) {
    asm volatile("cp.async.cg.shared.global [%0], [%1], 16;\n" :: "r"(dst), "l"(src));
}
__device__ __forceinline__ void cp_commit() { asm volatile("cp.async.commit_group;\n"); }
template<int N> __device__ __forceinline__ void cp_wait() {
    asm volatile("cp.async.wait_group %0;\n" :: "n"(N));
}
// D += A(16x8) * B(8x8), tf32 inputs (HW truncates raw fp32 bits), fp32 accum
__device__ __forceinline__ void mma8(float* c, const uint32_t* a, const uint32_t* b) {
    asm volatile("mma.sync.aligned.m16n8k8.row.col.f32.tf32.tf32.f32 "
                 "{%0,%1,%2,%3},{%4,%5,%6,%7},{%8,%9},{%0,%1,%2,%3};\n"
                 : "+f"(c[0]), "+f"(c[1]), "+f"(c[2]), "+f"(c[3])
                 : "r"(a[0]), "r"(a[1]), "r"(a[2]), "r"(a[3]), "r"(b[0]), "r"(b[1]));
}
// cheap 2-op split: hi = top-10-mantissa truncation (what the MMA keeps), lo = residue
__device__ __forceinline__ void split_tf32(float x, uint32_t& hi, uint32_t& lo) {
    uint32_t h = __float_as_uint(x) & 0xFFFFE000u;
    hi = h;
    lo = __float_as_uint(x - __uint_as_float(h));
}
// C += A*B with 3 mmas: lo*hi + hi*lo + hi*hi
__device__ __forceinline__ void mma3(float* c, const uint32_t* ah, const uint32_t* al,
                                     const uint32_t* bh, const uint32_t* bl) {
    mma8(c, al, bh);
    mma8(c, ah, bl);
    mma8(c, ah, bh);
}

// ================= main GEMM: C[M,N] = A[M,K] @ B[K,N] =================
// 64x64 output tile, 8 warps (256 threads) with in-CTA split-K:
//   warps 0-3 accumulate even BK-chunks, warps 4-7 odd BK-chunks
//   (identical per-warp inner loop to the proven 4-warp kernel),
// then the two partial 64x64 accumulators are combined through smem.
// Grid stays >=256 CTAs while warps/SM doubles -> latency hiding.
#define BM 64
#define BN 64
#define BK 16
#define ASTR 20   // (BK+4); 20 % 8 == 4  -> conflict-free A frags
#define BSTR 72   // (BN+8); 72 % 32 == 8 -> conflict-free B frags
#define REDSTR 33 // reduction stride: lane l hits bank l+j -> conflict-free

template<bool RELU>
__global__ __launch_bounds__(256) void gemm_tf32(
    const float* __restrict__ A, const float* __restrict__ B,
    float* __restrict__ C, int M, int N, int K) {
    __shared__ float As[2][2][BM * ASTR];   // [khalf][buf]
    __shared__ float Bs[2][2][BK * BSTR];
    const int t = threadIdx.x;
    const int warp = t >> 5;
    const int kw = warp >> 2;          // k-half: 0 or 1
    const int t2 = t & 127;            // thread id within half
    const int w2 = warp & 3, lane = t & 31, g = lane >> 2, tg = lane & 3;
    const int wm = (w2 & 1) * 32, wn = (w2 >> 1) * 32;
    const int rowBase = blockIdx.x * BM, colBase = blockIdx.y * BN;
    const int am = t2 >> 2, ak = (t2 & 3) * 4;   // A: 32 rows/pass, 2 passes
    const int bk = t2 >> 4, bn = (t2 & 15) * 4;  // B: 8 rows/pass, 2 passes

    float c[2][4][4] = {};

    auto copy_tiles = [&](int buf, int k0) {
        #pragma unroll
        for (int i = 0; i < 2; i++) {
            int m = am + i * 32;
            cpasync16(smem_u32(&As[kw][buf][m * ASTR + ak]),
                      &A[(size_t)(rowBase + m) * K + k0 + ak]);
        }
        #pragma unroll
        for (int i = 0; i < 2; i++) {
            int k = bk + i * 8;
            cpasync16(smem_u32(&Bs[kw][buf][k * BSTR + bn]),
                      &B[(size_t)(k0 + k) * N + colBase + bn]);
        }
        cp_commit();
    };

    const int iters = K / (2 * BK);    // chunks per half
    const int kbase = kw * BK;         // half 0: 0,32,64,..; half 1: 16,48,..
    copy_tiles(0, kbase);
    for (int i = 0; i < iters; i++) {
        const int cur = i & 1;
        if (i + 1 < iters) { copy_tiles(cur ^ 1, kbase + (i + 1) * 2 * BK); cp_wait<1>(); }
        else               { cp_wait<0>(); }
        __syncthreads();
        #pragma unroll
        for (int kk = 0; kk < BK; kk += 8) {
            uint32_t ah[2][4], al[2][4], bh[4][2], bl[4][2];
            #pragma unroll
            for (int mt = 0; mt < 2; mt++) {
                const float* base = &As[kw][cur][(wm + mt * 16) * ASTR + kk];
                split_tf32(base[g * ASTR + tg],           ah[mt][0], al[mt][0]);
                split_tf32(base[(g + 8) * ASTR + tg],     ah[mt][1], al[mt][1]);
                split_tf32(base[g * ASTR + tg + 4],       ah[mt][2], al[mt][2]);
                split_tf32(base[(g + 8) * ASTR + tg + 4], ah[mt][3], al[mt][3]);
            }
            #pragma unroll
            for (int nt = 0; nt < 4; nt++) {
                const float* base = &Bs[kw][cur][kk * BSTR + wn + nt * 8 + g];
                split_tf32(base[tg * BSTR],       bh[nt][0], bl[nt][0]);
                split_tf32(base[(tg + 4) * BSTR], bh[nt][1], bl[nt][1]);
            }
            #pragma unroll
            for (int mt = 0; mt < 2; mt++)
                #pragma unroll
                for (int nt = 0; nt < 4; nt++)
                    mma3(c[mt][nt], ah[mt], al[mt], bh[nt], bl[nt]);
        }
        __syncthreads();
    }

    // ---- combine the two k-half partials (smem, conflict-free stride) ----
    float* Red = &As[0][0][0];   // alias: 128*33 = 4224 floats <= As size (5120)
    if (kw == 1) {
        int o = 0;
        #pragma unroll
        for (int mt = 0; mt < 2; mt++)
            #pragma unroll
            for (int nt = 0; nt < 4; nt++)
                #pragma unroll
                for (int j = 0; j < 4; j++)
                    Red[t2 * REDSTR + o++] = c[mt][nt][j];
    }
    __syncthreads();
    if (kw == 0) {
        int o = 0;
        #pragma unroll
        for (int mt = 0; mt < 2; mt++)
            #pragma unroll
            for (int nt = 0; nt < 4; nt++)
                #pragma unroll
                for (int j = 0; j < 4; j++)
                    c[mt][nt][j] += Red[t2 * REDSTR + o++];
        // epilogue
        #pragma unroll
        for (int mt = 0; mt < 2; mt++) {
            #pragma unroll
            for (int nt = 0; nt < 4; nt++) {
                int r0 = rowBase + wm + mt * 16 + g;
                int col = colBase + wn + nt * 8 + tg * 2;
                float2 v0 = {c[mt][nt][0], c[mt][nt][1]};
                float2 v1 = {c[mt][nt][2], c[mt][nt][3]};
                if (RELU) {
                    v0.x = fmaxf(v0.x, 0.f); v0.y = fmaxf(v0.y, 0.f);
                    v1.x = fmaxf(v1.x, 0.f); v1.y = fmaxf(v1.y, 0.f);
                }
                *(float2*)&C[(size_t)r0 * N + col] = v0;
                *(float2*)&C[(size_t)(r0 + 8) * N + col] = v1;
            }
        }
    }
}

// ================= fused flash attention (unchanged from round 10) =================
#define QSTR 68   // 68 % 8 == 4: conflict-free A-frag rows
#define VSTR 72   // 72 % 32 == 8: conflict-free B-frag rows
#define PSTR 68
#define SMFL ((3*64*QSTR + 2*64*VSTR + 64*PSTR) * 4)   // 106,496 bytes

__global__ __launch_bounds__(128) void flash_tf32(
    const float* __restrict__ Q, const float* __restrict__ K,
    const float* __restrict__ V, float* __restrict__ O, int causal) {
    extern __shared__ float sm[];
    float* Qs  = sm;
    float* Ks0 = Qs  + 64 * QSTR;
    float* Ks1 = Ks0 + 64 * QSTR;
    float* Vs0 = Ks1 + 64 * QSTR;
    float* Vs1 = Vs0 + 64 * VSTR;
    float* Ps  = Vs1 + 64 * VSTR;

    const int bh = blockIdx.y, b = bh >> 3, h = bh & 7;
    const int q0 = blockIdx.x * 64;
    const int t = threadIdx.x, warp = t >> 5, lane = t & 31, g = lane >> 2, tg = lane & 3;
    const int wq = warp * 16;
    const int lr = t >> 4, ld4 = (t & 15) * 4;

    auto loadKV = [&](float* Kd, float* Vd, int k0) {
        #pragma unroll
        for (int i = 0; i < 8; i++) {
            int r = lr + i * 8;
            cpasync16(smem_u32(&Kd[r * QSTR + ld4]),
                      &K[(size_t)((b * Sq + k0 + r) * Dm) + h * 64 + ld4]);
            cpasync16(smem_u32(&Vd[r * VSTR + ld4]),
                      &V[(size_t)((b * Sq + k0 + r) * Dm) + h * 64 + ld4]);
        }
    };

    #pragma unroll
    for (int i = 0; i < 8; i++) {
        int r = lr + i * 8;
        cpasync16(smem_u32(&Qs[r * QSTR + ld4]),
                  &Q[(size_t)((b * Sq + q0 + r) * Dm) + h * 64 + ld4]);
    }
    loadKV(Ks0, Vs0, 0);
    cp_commit();

    const int nkt = causal ? (blockIdx.x + 1) : (Sq / 64);

    cp_wait<0>();
    __syncthreads();

    // ---- pre-split Q fragments (loop-invariant across k-tiles) ----
    uint32_t qh[8][4], ql[8][4];
    #pragma unroll
    for (int k8 = 0; k8 < 8; k8++) {
        const float* ab = &Qs[wq * QSTR + k8 * 8];
        split_tf32(ab[g * QSTR + tg],           qh[k8][0], ql[k8][0]);
        split_tf32(ab[(g + 8) * QSTR + tg],     qh[k8][1], ql[k8][1]);
        split_tf32(ab[g * QSTR + tg + 4],       qh[k8][2], ql[k8][2]);
        split_tf32(ab[(g + 8) * QSTR + tg + 4], qh[k8][3], ql[k8][3]);
    }

    if (nkt > 1) { loadKV(Ks1, Vs1, 64); cp_commit(); }

    float o[8][4] = {};
    float m0p = -1e30f, m1p = -1e30f;
    float l0 = 0.f, l1 = 0.f;

    for (int kt = 0; kt < nkt; kt++) {
        float* Kc = (kt & 1) ? Ks1 : Ks0;
        float* Vc = (kt & 1) ? Vs1 : Vs0;
        if (kt > 0) { cp_wait<0>(); __syncthreads(); }
        if (kt + 1 < nkt) {
            loadKV((kt & 1) ? Ks0 : Ks1, (kt & 1) ? Vs0 : Vs1, (kt + 1) * 64);
            cp_commit();
        }
        // ---- S = Q . K^T ----
        float s[8][4] = {};
        #pragma unroll
        for (int k8 = 0; k8 < 8; k8++) {
            const int kk = k8 * 8;
            #pragma unroll
            for (int nt = 0; nt < 8; nt++) {
                uint32_t bhf[2], blf[2];
                const float* bb = &Kc[(nt * 8 + g) * QSTR + kk];
                split_tf32(bb[tg],     bhf[0], blf[0]);
                split_tf32(bb[tg + 4], bhf[1], blf[1]);
                mma3(s[nt], qh[k8], ql[k8], bhf, blf);
            }
        }
        // ---- scale + (diagonal-tile) causal mask ----
        const bool diag = causal && (kt == blockIdx.x);
        #pragma unroll
        for (int nt = 0; nt < 8; nt++) {
            s[nt][0] *= 0.125f; s[nt][1] *= 0.125f;
            s[nt][2] *= 0.125f; s[nt][3] *= 0.125f;
            if (diag) {
                int col = kt * 64 + nt * 8 + tg * 2;
                int r0 = q0 + wq + g, r1 = r0 + 8;
                if (col     > r0) s[nt][0] = NEGV;
                if (col + 1 > r0) s[nt][1] = NEGV;
                if (col     > r1) s[nt][2] = NEGV;
                if (col + 1 > r1) s[nt][3] = NEGV;
            }
        }
        // ---- online softmax ----
        float m0 = -1e30f, m1 = -1e30f;
        #pragma unroll
        for (int nt = 0; nt < 8; nt++) {
            m0 = fmaxf(m0, fmaxf(s[nt][0], s[nt][1]));
            m1 = fmaxf(m1, fmaxf(s[nt][2], s[nt][3]));
        }
        m0 = fmaxf(m0, __shfl_xor_sync(0xffffffffu, m0, 1));
        m0 = fmaxf(m0, __shfl_xor_sync(0xffffffffu, m0, 2));
        m1 = fmaxf(m1, __shfl_xor_sync(0xffffffffu, m1, 1));
        m1 = fmaxf(m1, __shfl_xor_sync(0xffffffffu, m1, 2));
        float mn0 = fmaxf(m0p, m0), mn1 = fmaxf(m1p, m1);
        float a0 = __expf(m0p - mn0), a1 = __expf(m1p - mn1);
        m0p = mn0; m1p = mn1;

        float rs0 = 0.f, rs1 = 0.f;
        #pragma unroll
        for (int nt = 0; nt < 8; nt++) {
            float p0 = __expf(s[nt][0] - mn0), p1 = __expf(s[nt][1] - mn0);
            float p2 = __expf(s[nt][2] - mn1), p3 = __expf(s[nt][3] - mn1);
            rs0 += p0 + p1; rs1 += p2 + p3;
            *(float2*)&Ps[(wq + g) * PSTR + nt * 8 + tg * 2]     = make_float2(p0, p1);
            *(float2*)&Ps[(wq + g + 8) * PSTR + nt * 8 + tg * 2] = make_float2(p2, p3);
        }
        rs0 += __shfl_xor_sync(0xffffffffu, rs0, 1);
        rs0 += __shfl_xor_sync(0xffffffffu, rs0, 2);
        rs1 += __shfl_xor_sync(0xffffffffu, rs1, 1);
        rs1 += __shfl_xor_sync(0xffffffffu, rs1, 2);
        l0 = l0 * a0 + rs0;
        l1 = l1 * a1 + rs1;
        #pragma unroll
        for (int nt = 0; nt < 8; nt++) {
            o[nt][0] *= a0; o[nt][1] *= a0;
            o[nt][2] *= a1; o[nt][3] *= a1;
        }
        __syncwarp();
        // ---- O += P . V ----
        #pragma unroll
        for (int kk = 0; kk < 64; kk += 8) {
            uint32_t ah[4], al[4];
            const float* ab = &Ps[wq * PSTR + kk];
            split_tf32(ab[g * PSTR + tg],           ah[0], al[0]);
            split_tf32(ab[(g + 8) * PSTR + tg],     ah[1], al[1]);
            split_tf32(ab[g * PSTR + tg + 4],       ah[2], al[2]);
            split_tf32(ab[(g + 8) * PSTR + tg + 4], ah[3], al[3]);
            #pragma unroll
            for (int nt = 0; nt < 8; nt++) {
                uint32_t bhf[2], blf[2];
                const float* bb = &Vc[kk * VSTR + nt * 8 + g];
                split_tf32(bb[tg * VSTR],       bhf[0], blf[0]);
                split_tf32(bb[(tg + 4) * VSTR], bhf[1], blf[1]);
                mma3(o[nt], ah, al, bhf, blf);
            }
        }
        __syncwarp();
    }
    // ---- epilogue ----
    float inv0 = 1.0f / l0, inv1 = 1.0f / l1;
    #pragma unroll
    for (int nt = 0; nt < 8; nt++) {
        int col = h * 64 + nt * 8 + tg * 2;
        size_t r0 = (size_t)(b * Sq + q0 + wq + g);
        *(float2*)&O[r0 * Dm + col] = make_float2(o[nt][0] * inv0, o[nt][1] * inv0);
        *(float2*)&O[(r0 + 8) * Dm + col] = make_float2(o[nt][2] * inv1, o[nt][3] * inv1);
    }
}

// ---------------- out = LayerNorm(X + R) ----------------
__global__ void add_ln_kernel(const float* __restrict__ X, const float* __restrict__ R,
                              float* __restrict__ O) {
    const int row = blockIdx.x;
    const int t = threadIdx.x;
    const float* x = X + (size_t)row * Dm;
    const float* r = R + (size_t)row * Dm;
    float v0 = x[t] + r[t], v1 = x[t + 256] + r[t + 256];
    __shared__ float red[256];
    red[t] = v0 + v1; __syncthreads();
    for (int s = 128; s > 0; s >>= 1) { if (t < s) red[t] += red[t + s]; __syncthreads(); }
    float mean = red[0] * (1.0f / Dm); __syncthreads();
    float d0 = v0 - mean, d1 = v1 - mean;
    red[t] = d0 * d0 + d1 * d1; __syncthreads();
    for (int s = 128; s > 0; s >>= 1) { if (t < s) red[t] += red[t + s]; __syncthreads(); }
    float inv = rsqrtf(red[0] * (1.0f / Dm) + 1e-5f);
    float* o = O + (size_t)row * Dm;
    o[t] = d0 * inv; o[t + 256] = d1 * inv;
}

// ---------------- host orchestration ----------------
struct Bufs { float *Q, *K, *V, *Ctx, *Tmp, *Ffn, *Enc, *Dec; };

static void attn_block(const float* xq, const float* xkv,
                       const float* Wq, const float* Wk, const float* Wv, const float* Wo,
                       int causal, float* dst, const Bufs& bf) {
    dim3 gP(TOK / BM, Dm / BN);
    gemm_tf32<false><<<gP, 256>>>(xq,  Wq, bf.Q, TOK, Dm, Dm);
    gemm_tf32<false><<<gP, 256>>>(xkv, Wk, bf.K, TOK, Dm, Dm);
    gemm_tf32<false><<<gP, 256>>>(xkv, Wv, bf.V, TOK, Dm, Dm);
    flash_tf32<<<dim3(Sq / 64, Bz * Hh), 128, SMFL>>>(bf.Q, bf.K, bf.V, bf.Ctx, causal);
    gemm_tf32<false><<<gP, 256>>>(bf.Ctx, Wo, bf.Tmp, TOK, Dm, Dm);
    add_ln_kernel<<<TOK, 256>>>(bf.Tmp, xq, dst);
}

static void ffn_block(const float* x, const float* W1, const float* W2,
                      float* dst, const Bufs& bf) {
    gemm_tf32<true ><<<dim3(TOK / BM, FF / BN), 256>>>(x, W1, bf.Ffn, TOK, FF, Dm);
    gemm_tf32<false><<<dim3(TOK / BM, Dm / BN), 256>>>(bf.Ffn, W2, bf.Tmp, TOK, Dm, FF);
    add_ln_kernel<<<TOK, 256>>>(bf.Tmp, x, dst);
}

extern "C" void kernel_launch(void* const* d_in, const int* in_sizes, int n_in,
                              void* d_out, int out_size) {
    const float* enc_in  = (const float*)d_in[0];
    const float* dec_in  = (const float*)d_in[1];
    // d_in[2] is dec_self_attn_mask: exactly tril(ones) per the reference -> causal flag
    const float* enc_Wq  = (const float*)d_in[3];
    const float* enc_Wk  = (const float*)d_in[4];
    const float* enc_Wv  = (const float*)d_in[5];
    const float* enc_Wo  = (const float*)d_in[6];
    const float* enc_W1  = (const float*)d_in[7];
    const float* enc_W2  = (const float*)d_in[8];
    const float* sa_Wq   = (const float*)d_in[9];
    const float* sa_Wk   = (const float*)d_in[10];
    const float* sa_Wv   = (const float*)d_in[11];
    const float* sa_Wo   = (const float*)d_in[12];
    const float* ca_Wq   = (const float*)d_in[13];
    const float* ca_Wk   = (const float*)d_in[14];
    const float* ca_Wv   = (const float*)d_in[15];
    const float* ca_Wo   = (const float*)d_in[16];
    const float* dec_W1  = (const float*)d_in[17];
    const float* dec_W2  = (const float*)d_in[18];

    cudaFuncSetAttribute(flash_tf32, cudaFuncAttributeMaxDynamicSharedMemorySize, SMFL);

    Bufs bf;
    cudaGetSymbolAddress((void**)&bf.Q,   g_Q);
    cudaGetSymbolAddress((void**)&bf.K,   g_K);
    cudaGetSymbolAddress((void**)&bf.V,   g_V);
    cudaGetSymbolAddress((void**)&bf.Ctx, g_Ctx);
    cudaGetSymbolAddress((void**)&bf.Tmp, g_Tmp);
    cudaGetSymbolAddress((void**)&bf.Ffn, g_Ffn);
    cudaGetSymbolAddress((void**)&bf.Enc, g_Enc);
    cudaGetSymbolAddress((void**)&bf.Dec, g_Dec);

    const size_t WP  = (size_t)Dm * Dm;
    const size_t W1S = (size_t)Dm * FF;
    const size_t W2S = (size_t)FF * Dm;

    // ---- encoder stack ----
    const float* src = enc_in;
    for (int i = 0; i < NL; i++) {
        attn_block(src, src, enc_Wq + i * WP, enc_Wk + i * WP, enc_Wv + i * WP,
                   enc_Wo + i * WP, 0, bf.Enc, bf);
        ffn_block(bf.Enc, enc_W1 + i * W1S, enc_W2 + i * W2S, bf.Enc, bf);
        src = bf.Enc;
    }

    // ---- decoder stack ----
    const float* dsrc = dec_in;
    for (int i = 0; i < NL; i++) {
        attn_block(dsrc, dsrc, sa_Wq + i * WP, sa_Wk + i * WP, sa_Wv + i * WP,
                   sa_Wo + i * WP, 1, bf.Dec, bf);
        attn_block(bf.Dec, bf.Enc, ca_Wq + i * WP, ca_Wk + i * WP, ca_Wv + i * WP,
                   ca_Wo + i * WP, 0, bf.Dec, bf);
        float* out = (i == NL - 1) ? (float*)d_out : bf.Dec;
        ffn_block(bf.Dec, dec_W1 + i * W1S, dec_W2 + i * W2S, out, bf);
        dsrc = bf.Dec;
    }
}

// round 12
// speedup vs baseline: 1.0008x; 1.0008x over previous
#include <cuda_runtime.h>
#include <cstdint>

#define Dm 512
#define Sq 512
#define Bz 4
#define Hh 8
#define FF 2048
#define NL 6
#define TOK (Bz*Sq)        // 2048 tokens
#define NEGV (-1000000000.0f)

// ---------------- scratch (no allocations allowed) ----------------
__device__ float g_Q  [TOK*Dm];
__device__ float g_K  [TOK*Dm];
__device__ float g_V  [TOK*Dm];
__device__ float g_Ctx[TOK*Dm];
__device__ float g_Tmp[TOK*Dm];
__device__ float g_Ffn[TOK*FF];
__device__ float g_Enc[TOK*Dm];
__device__ float g_Dec[TOK*Dm];

// ---------------- PTX helpers ----------------
__device__ __forceinline__ uint32_t smem_u32(const void* p) {
    return (uint32_t)__cvta_generic_to_shared(p);
}
__device__ __forceinline__ void cpasync16(uint32_t dst, const void* src) {
    asm volatile("cp.async.cg.shared.global [%0], [%1], 16;\n" :: "r"(dst), "l"(src));
}
__device__ __forceinline__ void cp_commit() { asm volatile("cp.async.commit_group;\n"); }
template<int N> __device__ __forceinline__ void cp_wait() {
    asm volatile("cp.async.wait_group %0;\n" :: "n"(N));
}
// D += A(16x8) * B(8x8), tf32 inputs (HW truncates raw fp32 bits), fp32 accum
__device__ __forceinline__ void mma8(float* c, const uint32_t* a, const uint32_t* b) {
    asm volatile("mma.sync.aligned.m16n8k8.row.col.f32.tf32.tf32.f32 "
                 "{%0,%1,%2,%3},{%4,%5,%6,%7},{%8,%9},{%0,%1,%2,%3};\n"
                 : "+f"(c[0]), "+f"(c[1]), "+f"(c[2]), "+f"(c[3])
                 : "r"(a[0]), "r"(a[1]), "r"(a[2]), "r"(a[3]), "r"(b[0]), "r"(b[1]));
}
// cheap 2-op split: hi = top-10-mantissa truncation (what the MMA keeps), lo = residue
__device__ __forceinline__ void split_tf32(float x, uint32_t& hi, uint32_t& lo) {
    uint32_t h = __float_as_uint(x) & 0xFFFFE000u;
    hi = h;
    lo = __float_as_uint(x - __uint_as_float(h));
}
// C += A*B with 3 mmas: lo*hi + hi*lo + hi*hi
__device__ __forceinline__ void mma3(float* c, const uint32_t* ah, const uint32_t* al,
                                     const uint32_t* bh, const uint32_t* bl) {
    mma8(c, al, bh);
    mma8(c, ah, bl);
    mma8(c, ah, bh);
}

// ================= main GEMM: C[M,N] = A[M,K] @ B[K,N] =================
// 64x64 output tile, 8 warps (256 threads) with in-CTA split-K:
//   warps 0-3 accumulate even BK-chunks, warps 4-7 odd BK-chunks
//   (identical per-warp inner loop to the proven 4-warp kernel),
// then the two partial 64x64 accumulators are combined through smem.
// Grid stays >=256 CTAs while warps/SM doubles -> latency hiding.
#define BM 64
#define BN 64
#define BK 16
#define ASTR 20   // (BK+4); 20 % 8 == 4  -> conflict-free A frags
#define BSTR 72   // (BN+8); 72 % 32 == 8 -> conflict-free B frags
#define REDSTR 33 // reduction stride: lane l hits bank l+j -> conflict-free

template<bool RELU>
__global__ __launch_bounds__(256) void gemm_tf32(
    const float* __restrict__ A, const float* __restrict__ B,
    float* __restrict__ C, int M, int N, int K) {
    __shared__ float As[2][2][BM * ASTR];   // [khalf][buf]
    __shared__ float Bs[2][2][BK * BSTR];
    const int t = threadIdx.x;
    const int warp = t >> 5;
    const int kw = warp >> 2;          // k-half: 0 or 1
    const int t2 = t & 127;            // thread id within half
    const int w2 = warp & 3, lane = t & 31, g = lane >> 2, tg = lane & 3;
    const int wm = (w2 & 1) * 32, wn = (w2 >> 1) * 32;
    const int rowBase = blockIdx.x * BM, colBase = blockIdx.y * BN;
    const int am = t2 >> 2, ak = (t2 & 3) * 4;   // A: 32 rows/pass, 2 passes
    const int bk = t2 >> 4, bn = (t2 & 15) * 4;  // B: 8 rows/pass, 2 passes

    float c[2][4][4] = {};

    auto copy_tiles = [&](int buf, int k0) {
        #pragma unroll
        for (int i = 0; i < 2; i++) {
            int m = am + i * 32;
            cpasync16(smem_u32(&As[kw][buf][m * ASTR + ak]),
                      &A[(size_t)(rowBase + m) * K + k0 + ak]);
        }
        #pragma unroll
        for (int i = 0; i < 2; i++) {
            int k = bk + i * 8;
            cpasync16(smem_u32(&Bs[kw][buf][k * BSTR + bn]),
                      &B[(size_t)(k0 + k) * N + colBase + bn]);
        }
        cp_commit();
    };

    const int iters = K / (2 * BK);    // chunks per half
    const int kbase = kw * BK;         // half 0: 0,32,64,..; half 1: 16,48,..
    copy_tiles(0, kbase);
    for (int i = 0; i < iters; i++) {
        const int cur = i & 1;
        if (i + 1 < iters) { copy_tiles(cur ^ 1, kbase + (i + 1) * 2 * BK); cp_wait<1>(); }
        else               { cp_wait<0>(); }
        __syncthreads();
        #pragma unroll
        for (int kk = 0; kk < BK; kk += 8) {
            uint32_t ah[2][4], al[2][4], bh[4][2], bl[4][2];
            #pragma unroll
            for (int mt = 0; mt < 2; mt++) {
                const float* base = &As[kw][cur][(wm + mt * 16) * ASTR + kk];
                split_tf32(base[g * ASTR + tg],           ah[mt][0], al[mt][0]);
                split_tf32(base[(g + 8) * ASTR + tg],     ah[mt][1], al[mt][1]);
                split_tf32(base[g * ASTR + tg + 4],       ah[mt][2], al[mt][2]);
                split_tf32(base[(g + 8) * ASTR + tg + 4], ah[mt][3], al[mt][3]);
            }
            #pragma unroll
            for (int nt = 0; nt < 4; nt++) {
                const float* base = &Bs[kw][cur][kk * BSTR + wn + nt * 8 + g];
                split_tf32(base[tg * BSTR],       bh[nt][0], bl[nt][0]);
                split_tf32(base[(tg + 4) * BSTR], bh[nt][1], bl[nt][1]);
            }
            #pragma unroll
            for (int mt = 0; mt < 2; mt++)
                #pragma unroll
                for (int nt = 0; nt < 4; nt++)
                    mma3(c[mt][nt], ah[mt], al[mt], bh[nt], bl[nt]);
        }
        __syncthreads();
    }

    // ---- combine the two k-half partials (smem, conflict-free stride) ----
    float* Red = &As[0][0][0];   // alias: 128*33 = 4224 floats <= As size (5120)
    if (kw == 1) {
        int o = 0;
        #pragma unroll
        for (int mt = 0; mt < 2; mt++)
            #pragma unroll
            for (int nt = 0; nt < 4; nt++)
                #pragma unroll
                for (int j = 0; j < 4; j++)
                    Red[t2 * REDSTR + o++] = c[mt][nt][j];
    }
    __syncthreads();
    if (kw == 0) {
        int o = 0;
        #pragma unroll
        for (int mt = 0; mt < 2; mt++)
            #pragma unroll
            for (int nt = 0; nt < 4; nt++)
                #pragma unroll
                for (int j = 0; j < 4; j++)
                    c[mt][nt][j] += Red[t2 * REDSTR + o++];
        // epilogue
        #pragma unroll
        for (int mt = 0; mt < 2; mt++) {
            #pragma unroll
            for (int nt = 0; nt < 4; nt++) {
                int r0 = rowBase + wm + mt * 16 + g;
                int col = colBase + wn + nt * 8 + tg * 2;
                float2 v0 = {c[mt][nt][0], c[mt][nt][1]};
                float2 v1 = {c[mt][nt][2], c[mt][nt][3]};
                if (RELU) {
                    v0.x = fmaxf(v0.x, 0.f); v0.y = fmaxf(v0.y, 0.f);
                    v1.x = fmaxf(v1.x, 0.f); v1.y = fmaxf(v1.y, 0.f);
                }
                *(float2*)&C[(size_t)r0 * N + col] = v0;
                *(float2*)&C[(size_t)(r0 + 8) * N + col] = v1;
            }
        }
    }
}

// ================= fused flash attention (unchanged from round 10) =================
#define QSTR 68   // 68 % 8 == 4: conflict-free A-frag rows
#define VSTR 72   // 72 % 32 == 8: conflict-free B-frag rows
#define PSTR 68
#define SMFL ((3*64*QSTR + 2*64*VSTR + 64*PSTR) * 4)   // 106,496 bytes

__global__ __launch_bounds__(128) void flash_tf32(
    const float* __restrict__ Q, const float* __restrict__ K,
    const float* __restrict__ V, float* __restrict__ O, int causal) {
    extern __shared__ float sm[];
    float* Qs  = sm;
    float* Ks0 = Qs  + 64 * QSTR;
    float* Ks1 = Ks0 + 64 * QSTR;
    float* Vs0 = Ks1 + 64 * QSTR;
    float* Vs1 = Vs0 + 64 * VSTR;
    float* Ps  = Vs1 + 64 * VSTR;

    const int bh = blockIdx.y, b = bh >> 3, h = bh & 7;
    const int q0 = blockIdx.x * 64;
    const int t = threadIdx.x, warp = t >> 5, lane = t & 31, g = lane >> 2, tg = lane & 3;
    const int wq = warp * 16;
    const int lr = t >> 4, ld4 = (t & 15) * 4;

    auto loadKV = [&](float* Kd, float* Vd, int k0) {
        #pragma unroll
        for (int i = 0; i < 8; i++) {
            int r = lr + i * 8;
            cpasync16(smem_u32(&Kd[r * QSTR + ld4]),
                      &K[(size_t)((b * Sq + k0 + r) * Dm) + h * 64 + ld4]);
            cpasync16(smem_u32(&Vd[r * VSTR + ld4]),
                      &V[(size_t)((b * Sq + k0 + r) * Dm) + h * 64 + ld4]);
        }
    };

    #pragma unroll
    for (int i = 0; i < 8; i++) {
        int r = lr + i * 8;
        cpasync16(smem_u32(&Qs[r * QSTR + ld4]),
                  &Q[(size_t)((b * Sq + q0 + r) * Dm) + h * 64 + ld4]);
    }
    loadKV(Ks0, Vs0, 0);
    cp_commit();

    const int nkt = causal ? (blockIdx.x + 1) : (Sq / 64);

    cp_wait<0>();
    __syncthreads();

    // ---- pre-split Q fragments (loop-invariant across k-tiles) ----
    uint32_t qh[8][4], ql[8][4];
    #pragma unroll
    for (int k8 = 0; k8 < 8; k8++) {
        const float* ab = &Qs[wq * QSTR + k8 * 8];
        split_tf32(ab[g * QSTR + tg],           qh[k8][0], ql[k8][0]);
        split_tf32(ab[(g + 8) * QSTR + tg],     qh[k8][1], ql[k8][1]);
        split_tf32(ab[g * QSTR + tg + 4],       qh[k8][2], ql[k8][2]);
        split_tf32(ab[(g + 8) * QSTR + tg + 4], qh[k8][3], ql[k8][3]);
    }

    if (nkt > 1) { loadKV(Ks1, Vs1, 64); cp_commit(); }

    float o[8][4] = {};
    float m0p = -1e30f, m1p = -1e30f;
    float l0 = 0.f, l1 = 0.f;

    for (int kt = 0; kt < nkt; kt++) {
        float* Kc = (kt & 1) ? Ks1 : Ks0;
        float* Vc = (kt & 1) ? Vs1 : Vs0;
        if (kt > 0) { cp_wait<0>(); __syncthreads(); }
        if (kt + 1 < nkt) {
            loadKV((kt & 1) ? Ks0 : Ks1, (kt & 1) ? Vs0 : Vs1, (kt + 1) * 64);
            cp_commit();
        }
        // ---- S = Q . K^T ----
        float s[8][4] = {};
        #pragma unroll
        for (int k8 = 0; k8 < 8; k8++) {
            const int kk = k8 * 8;
            #pragma unroll
            for (int nt = 0; nt < 8; nt++) {
                uint32_t bhf[2], blf[2];
                const float* bb = &Kc[(nt * 8 + g) * QSTR + kk];
                split_tf32(bb[tg],     bhf[0], blf[0]);
                split_tf32(bb[tg + 4], bhf[1], blf[1]);
                mma3(s[nt], qh[k8], ql[k8], bhf, blf);
            }
        }
        // ---- scale + (diagonal-tile) causal mask ----
        const bool diag = causal && (kt == blockIdx.x);
        #pragma unroll
        for (int nt = 0; nt < 8; nt++) {
            s[nt][0] *= 0.125f; s[nt][1] *= 0.125f;
            s[nt][2] *= 0.125f; s[nt][3] *= 0.125f;
            if (diag) {
                int col = kt * 64 + nt * 8 + tg * 2;
                int r0 = q0 + wq + g, r1 = r0 + 8;
                if (col     > r0) s[nt][0] = NEGV;
                if (col + 1 > r0) s[nt][1] = NEGV;
                if (col     > r1) s[nt][2] = NEGV;
                if (col + 1 > r1) s[nt][3] = NEGV;
            }
        }
        // ---- online softmax ----
        float m0 = -1e30f, m1 = -1e30f;
        #pragma unroll
        for (int nt = 0; nt < 8; nt++) {
            m0 = fmaxf(m0, fmaxf(s[nt][0], s[nt][1]));
            m1 = fmaxf(m1, fmaxf(s[nt][2], s[nt][3]));
        }
        m0 = fmaxf(m0, __shfl_xor_sync(0xffffffffu, m0, 1));
        m0 = fmaxf(m0, __shfl_xor_sync(0xffffffffu, m0, 2));
        m1 = fmaxf(m1, __shfl_xor_sync(0xffffffffu, m1, 1));
        m1 = fmaxf(m1, __shfl_xor_sync(0xffffffffu, m1, 2));
        float mn0 = fmaxf(m0p, m0), mn1 = fmaxf(m1p, m1);
        float a0 = __expf(m0p - mn0), a1 = __expf(m1p - mn1);
        m0p = mn0; m1p = mn1;

        float rs0 = 0.f, rs1 = 0.f;
        #pragma unroll
        for (int nt = 0; nt < 8; nt++) {
            float p0 = __expf(s[nt][0] - mn0), p1 = __expf(s[nt][1] - mn0);
            float p2 = __expf(s[nt][2] - mn1), p3 = __expf(s[nt][3] - mn1);
            rs0 += p0 + p1; rs1 += p2 + p3;
            *(float2*)&Ps[(wq + g) * PSTR + nt * 8 + tg * 2]     = make_float2(p0, p1);
            *(float2*)&Ps[(wq + g + 8) * PSTR + nt * 8 + tg * 2] = make_float2(p2, p3);
        }
        rs0 += __shfl_xor_sync(0xffffffffu, rs0, 1);
        rs0 += __shfl_xor_sync(0xffffffffu, rs0, 2);
        rs1 += __shfl_xor_sync(0xffffffffu, rs1, 1);
        rs1 += __shfl_xor_sync(0xffffffffu, rs1, 2);
        l0 = l0 * a0 + rs0;
        l1 = l1 * a1 + rs1;
        #pragma unroll
        for (int nt = 0; nt < 8; nt++) {
            o[nt][0] *= a0; o[nt][1] *= a0;
            o[nt][2] *= a1; o[nt][3] *= a1;
        }
        __syncwarp();
        // ---- O += P . V ----
        #pragma unroll
        for (int kk = 0; kk < 64; kk += 8) {
            uint32_t ah[4], al[4];
            const float* ab = &Ps[wq * PSTR + kk];
            split_tf32(ab[g * PSTR + tg],           ah[0], al[0]);
            split_tf32(ab[(g + 8) * PSTR + tg],     ah[1], al[1]);
            split_tf32(ab[g * PSTR + tg + 4],       ah[2], al[2]);
            split_tf32(ab[(g + 8) * PSTR + tg + 4], ah[3], al[3]);
            #pragma unroll
            for (int nt = 0; nt < 8; nt++) {
                uint32_t bhf[2], blf[2];
                const float* bb = &Vc[kk * VSTR + nt * 8 + g];
                split_tf32(bb[tg * VSTR],       bhf[0], blf[0]);
                split_tf32(bb[(tg + 4) * VSTR], bhf[1], blf[1]);
                mma3(o[nt], ah, al, bhf, blf);
            }
        }
        __syncwarp();
    }
    // ---- epilogue ----
    float inv0 = 1.0f / l0, inv1 = 1.0f / l1;
    #pragma unroll
    for (int nt = 0; nt < 8; nt++) {
        int col = h * 64 + nt * 8 + tg * 2;
        size_t r0 = (size_t)(b * Sq + q0 + wq + g);
        *(float2*)&O[r0 * Dm + col] = make_float2(o[nt][0] * inv0, o[nt][1] * inv0);
        *(float2*)&O[(r0 + 8) * Dm + col] = make_float2(o[nt][2] * inv1, o[nt][3] * inv1);
    }
}

// ---------------- out = LayerNorm(X + R) ----------------
__global__ void add_ln_kernel(const float* __restrict__ X, const float* __restrict__ R,
                              float* __restrict__ O) {
    const int row = blockIdx.x;
    const int t = threadIdx.x;
    const float* x = X + (size_t)row * Dm;
    const float* r = R + (size_t)row * Dm;
    float v0 = x[t] + r[t], v1 = x[t + 256] + r[t + 256];
    __shared__ float red[256];
    red[t] = v0 + v1; __syncthreads();
    for (int s = 128; s > 0; s >>= 1) { if (t < s) red[t] += red[t + s]; __syncthreads(); }
    float mean = red[0] * (1.0f / Dm); __syncthreads();
    float d0 = v0 - mean, d1 = v1 - mean;
    red[t] = d0 * d0 + d1 * d1; __syncthreads();
    for (int s = 128; s > 0; s >>= 1) { if (t < s) red[t] += red[t + s]; __syncthreads(); }
    float inv = rsqrtf(red[0] * (1.0f / Dm) + 1e-5f);
    float* o = O + (size_t)row * Dm;
    o[t] = d0 * inv; o[t + 256] = d1 * inv;
}

// ---------------- host orchestration ----------------
struct Bufs { float *Q, *K, *V, *Ctx, *Tmp, *Ffn, *Enc, *Dec; };

static void attn_block(const float* xq, const float* xkv,
                       const float* Wq, const float* Wk, const float* Wv, const float* Wo,
                       int causal, float* dst, const Bufs& bf) {
    dim3 gP(TOK / BM, Dm / BN);
    gemm_tf32<false><<<gP, 256>>>(xq,  Wq, bf.Q, TOK, Dm, Dm);
    gemm_tf32<false><<<gP, 256>>>(xkv, Wk, bf.K, TOK, Dm, Dm);
    gemm_tf32<false><<<gP, 256>>>(xkv, Wv, bf.V, TOK, Dm, Dm);
    flash_tf32<<<dim3(Sq / 64, Bz * Hh), 128, SMFL>>>(bf.Q, bf.K, bf.V, bf.Ctx, causal);
    gemm_tf32<false><<<gP, 256>>>(bf.Ctx, Wo, bf.Tmp, TOK, Dm, Dm);
    add_ln_kernel<<<TOK, 256>>>(bf.Tmp, xq, dst);
}

static void ffn_block(const float* x, const float* W1, const float* W2,
                      float* dst, const Bufs& bf) {
    gemm_tf32<true ><<<dim3(TOK / BM, FF / BN), 256>>>(x, W1, bf.Ffn, TOK, FF, Dm);
    gemm_tf32<false><<<dim3(TOK / BM, Dm / BN), 256>>>(bf.Ffn, W2, bf.Tmp, TOK, Dm, FF);
    add_ln_kernel<<<TOK, 256>>>(bf.Tmp, x, dst);
}

extern "C" void kernel_launch(void* const* d_in, const int* in_sizes, int n_in,
                              void* d_out, int out_size) {
    const float* enc_in  = (const float*)d_in[0];
    const float* dec_in  = (const float*)d_in[1];
    // d_in[2] is dec_self_attn_mask: exactly tril(ones) per the reference -> causal flag
    const float* enc_Wq  = (const float*)d_in[3];
    const float* enc_Wk  = (const float*)d_in[4];
    const float* enc_Wv  = (const float*)d_in[5];
    const float* enc_Wo  = (const float*)d_in[6];
    const float* enc_W1  = (const float*)d_in[7];
    const float* enc_W2  = (const float*)d_in[8];
    const float* sa_Wq   = (const float*)d_in[9];
    const float* sa_Wk   = (const float*)d_in[10];
    const float* sa_Wv   = (const float*)d_in[11];
    const float* sa_Wo   = (const float*)d_in[12];
    const float* ca_Wq   = (const float*)d_in[13];
    const float* ca_Wk   = (const float*)d_in[14];
    const float* ca_Wv   = (const float*)d_in[15];
    const float* ca_Wo   = (const float*)d_in[16];
    const float* dec_W1  = (const float*)d_in[17];
    const float* dec_W2  = (const float*)d_in[18];

    cudaFuncSetAttribute(flash_tf32, cudaFuncAttributeMaxDynamicSharedMemorySize, SMFL);

    Bufs bf;
    cudaGetSymbolAddress((void**)&bf.Q,   g_Q);
    cudaGetSymbolAddress((void**)&bf.K,   g_K);
    cudaGetSymbolAddress((void**)&bf.V,   g_V);
    cudaGetSymbolAddress((void**)&bf.Ctx, g_Ctx);
    cudaGetSymbolAddress((void**)&bf.Tmp, g_Tmp);
    cudaGetSymbolAddress((void**)&bf.Ffn, g_Ffn);
    cudaGetSymbolAddress((void**)&bf.Enc, g_Enc);
    cudaGetSymbolAddress((void**)&bf.Dec, g_Dec);

    const size_t WP  = (size_t)Dm * Dm;
    const size_t W1S = (size_t)Dm * FF;
    const size_t W2S = (size_t)FF * Dm;

    // ---- encoder stack ----
    const float* src = enc_in;
    for (int i = 0; i < NL; i++) {
        attn_block(src, src, enc_Wq + i * WP, enc_Wk + i * WP, enc_Wv + i * WP,
                   enc_Wo + i * WP, 0, bf.Enc, bf);
        ffn_block(bf.Enc, enc_W1 + i * W1S, enc_W2 + i * W2S, bf.Enc, bf);
        src = bf.Enc;
    }

    // ---- decoder stack ----
    const float* dsrc = dec_in;
    for (int i = 0; i < NL; i++) {
        attn_block(dsrc, dsrc, sa_Wq + i * WP, sa_Wk + i * WP, sa_Wv + i * WP,
                   sa_Wo + i * WP, 1, bf.Dec, bf);
        attn_block(bf.Dec, bf.Enc, ca_Wq + i * WP, ca_Wk + i * WP, ca_Wv + i * WP,
                   ca_Wo + i * WP, 0, bf.Dec, bf);
        float* out = (i == NL - 1) ? (float*)d_out : bf.Dec;
        ffn_block(bf.Dec, dec_W1 + i * W1S, dec_W2 + i * W2S, out, bf);
        dsrc = bf.Dec;
    }
}

// round 14
// speedup vs baseline: 1.2632x; 1.2622x over previous
#include <cuda_runtime.h>
#include <cstdint>

#define Dm 512
#define Sq 512
#define Bz 4
#define Hh 8
#define FF 2048
#define NL 6
#define TOK (Bz*Sq)        // 2048 tokens
#define NEGV (-1000000000.0f)

// ---------------- scratch ----------------
__device__ float g_Q[TOK*Dm], g_K[TOK*Dm], g_V[TOK*Dm];
__device__ float g_Ctx[TOK*Dm], g_Tmp[TOK*Dm], g_Ffn[TOK*FF];
__device__ float g_Enc[TOK*Dm], g_Dec[TOK*Dm];

// ---------------- helpers ----------------
__device__ __forceinline__ uint32_t smem_u32(const void* p) {
    return (uint32_t)__cvta_generic_to_shared(p);
}
__device__ __forceinline__ void cpasync16(uint32_t dst, const void* src) {
    asm volatile("cp.async.cg.shared.global [%0], [%1], 16;\n" :: "r"(dst), "l"(src));
}
__device__ __forceinline__ void cp_commit() { asm volatile("cp.async.commit_group;\n"); }
template<int N> __device__ __forceinline__ void cp_wait() {
    asm volatile("cp.async.wait_group %0;\n" :: "n"(N));
}
// D += A(16x16) * B(16x8), bf16 inputs, fp32 accum
__device__ __forceinline__ void mmabf(float* c, const uint32_t* a, const uint32_t* b) {
    asm volatile("mma.sync.aligned.m16n8k16.row.col.f32.bf16.bf16.f32 "
                 "{%0,%1,%2,%3},{%4,%5,%6,%7},{%8,%9},{%0,%1,%2,%3};\n"
                 : "+f"(c[0]), "+f"(c[1]), "+f"(c[2]), "+f"(c[3])
                 : "r"(a[0]), "r"(a[1]), "r"(a[2]), "r"(a[3]), "r"(b[0]), "r"(b[1]));
}
// pack fp32 pair into bf16x2 (hi = truncation, lo = rn residue)
__device__ __forceinline__ void pack2(float f0, float f1, uint32_t& hi, uint32_t& lo) {
    uint32_t b0 = __float_as_uint(f0), b1 = __float_as_uint(f1);
    asm("prmt.b32 %0,%1,%2,0x7632;" : "=r"(hi) : "r"(b0), "r"(b1));
    float h0 = __uint_as_float(b0 & 0xFFFF0000u);
    float h1 = __uint_as_float(b1 & 0xFFFF0000u);
    asm("cvt.rn.bf16x2.f32 %0,%1,%2;" : "=r"(lo) : "f"(f1 - h1), "f"(f0 - h0));
}
// C += A*B: lo*hi + hi*lo + hi*hi
__device__ __forceinline__ void mma3(float* c, const uint32_t* ah, const uint32_t* al,
                                     const uint32_t* bh, const uint32_t* bl) {
    mmabf(c, al, bh);
    mmabf(c, ah, bl);
    mmabf(c, ah, bh);
}

// ================= main GEMM: C[M,N] = A[M,K] @ B[K,N] =================
// 64x64 block, BK=16 (= one k16 mma step), 4 warps (32x32 warp tiles), double-buffered.
#define BM 64
#define BN 64
#define BK 16
#define ASTR 24   // 24 % 32 in {0,24,16,8} per g -> conflict-free float2 A frags
#define BSTR 68   // 2*68 % 32 == 8 -> conflict-free scalar B frag rows
template<bool RELU>
__global__ __launch_bounds__(128) void gemm_bf16(
    const float* __restrict__ A, const float* __restrict__ B,
    float* __restrict__ C, int M, int N, int K) {
    __shared__ float As[2][BM * ASTR];
    __shared__ float Bs[2][BK * BSTR];
    const int t = threadIdx.x;
    const int warp = t >> 5, lane = t & 31, g = lane >> 2, tg = lane & 3;
    const int wm = (warp & 1) * 32, wn = (warp >> 1) * 32;
    const int rowBase = blockIdx.x * BM, colBase = blockIdx.y * BN;
    const int am = t >> 2, ak = (t & 3) * 4;
    const int bk = t >> 4, bn = (t & 15) * 4;

    float c[2][4][4] = {};

    auto copy_tiles = [&](int buf, int k0) {
        #pragma unroll
        for (int i = 0; i < 2; i++) {
            int m = am + i * 32;
            cpasync16(smem_u32(&As[buf][m * ASTR + ak]),
                      &A[(size_t)(rowBase + m) * K + k0 + ak]);
        }
        #pragma unroll
        for (int i = 0; i < 2; i++) {
            int k = bk + i * 8;
            cpasync16(smem_u32(&Bs[buf][k * BSTR + bn]),
                      &B[(size_t)(k0 + k) * N + colBase + bn]);
        }
        cp_commit();
    };

    const int iters = K / BK;
    copy_tiles(0, 0);
    for (int i = 0; i < iters; i++) {
        const int cur = i & 1;
        if (i + 1 < iters) { copy_tiles(cur ^ 1, (i + 1) * BK); cp_wait<1>(); }
        else               { cp_wait<0>(); }
        __syncthreads();
        // one k16 step
        uint32_t ah[2][4], al[2][4], bh[4][2], bl[4][2];
        #pragma unroll
        for (int mt = 0; mt < 2; mt++) {
            const float* base = &As[cur][(wm + mt * 16) * ASTR];
            float2 p0 = *(const float2*)&base[g * ASTR + 2 * tg];
            float2 p1 = *(const float2*)&base[(g + 8) * ASTR + 2 * tg];
            float2 p2 = *(const float2*)&base[g * ASTR + 2 * tg + 8];
            float2 p3 = *(const float2*)&base[(g + 8) * ASTR + 2 * tg + 8];
            pack2(p0.x, p0.y, ah[mt][0], al[mt][0]);
            pack2(p1.x, p1.y, ah[mt][1], al[mt][1]);
            pack2(p2.x, p2.y, ah[mt][2], al[mt][2]);
            pack2(p3.x, p3.y, ah[mt][3], al[mt][3]);
        }
        #pragma unroll
        for (int nt = 0; nt < 4; nt++) {
            const float* bb = &Bs[cur][wn + nt * 8 + g];
            float f0 = bb[(2 * tg) * BSTR],     f1 = bb[(2 * tg + 1) * BSTR];
            float f2 = bb[(2 * tg + 8) * BSTR], f3 = bb[(2 * tg + 9) * BSTR];
            pack2(f0, f1, bh[nt][0], bl[nt][0]);
            pack2(f2, f3, bh[nt][1], bl[nt][1]);
        }
        #pragma unroll
        for (int mt = 0; mt < 2; mt++)
            #pragma unroll
            for (int nt = 0; nt < 4; nt++)
                mma3(c[mt][nt], ah[mt], al[mt], bh[nt], bl[nt]);
        __syncthreads();
    }
    // epilogue
    #pragma unroll
    for (int mt = 0; mt < 2; mt++) {
        #pragma unroll
        for (int nt = 0; nt < 4; nt++) {
            int r0 = rowBase + wm + mt * 16 + g;
            int col = colBase + wn + nt * 8 + tg * 2;
            float2 v0 = {c[mt][nt][0], c[mt][nt][1]};
            float2 v1 = {c[mt][nt][2], c[mt][nt][3]};
            if (RELU) {
                v0.x = fmaxf(v0.x, 0.f); v0.y = fmaxf(v0.y, 0.f);
                v1.x = fmaxf(v1.x, 0.f); v1.y = fmaxf(v1.y, 0.f);
            }
            *(float2*)&C[(size_t)r0 * N + col] = v0;
            *(float2*)&C[(size_t)(r0 + 8) * N + col] = v1;
        }
    }
}

// ================= fused flash attention (bf16 3-split mma) =================
#define QSTR 72   // 72 % 32 == 8: conflict-free float2 A/B-row frags
#define VSTR 68   // 2*68 % 32 == 8: conflict-free scalar V frag rows
#define PSTR 72
#define SMFL ((4*64*QSTR + 2*64*VSTR) * 4)   // Qs,Ks0,Ks1,Ps @72 + Vs0,Vs1 @68 = 108,544 B

__global__ __launch_bounds__(128) void flash_bf16(
    const float* __restrict__ Q, const float* __restrict__ K,
    const float* __restrict__ V, float* __restrict__ O, int causal) {
    extern __shared__ float sm[];
    float* Qs  = sm;
    float* Ks0 = Qs  + 64 * QSTR;
    float* Ks1 = Ks0 + 64 * QSTR;
    float* Ps  = Ks1 + 64 * QSTR;
    float* Vs0 = Ps  + 64 * PSTR;
    float* Vs1 = Vs0 + 64 * VSTR;

    const int bh = blockIdx.y, b = bh >> 3, h = bh & 7;
    const int q0 = blockIdx.x * 64;
    const int t = threadIdx.x, warp = t >> 5, lane = t & 31, g = lane >> 2, tg = lane & 3;
    const int wq = warp * 16;
    const int lr = t >> 4, ld4 = (t & 15) * 4;

    auto loadKV = [&](float* Kd, float* Vd, int k0) {
        #pragma unroll
        for (int i = 0; i < 8; i++) {
            int r = lr + i * 8;
            cpasync16(smem_u32(&Kd[r * QSTR + ld4]),
                      &K[(size_t)((b * Sq + k0 + r) * Dm) + h * 64 + ld4]);
            cpasync16(smem_u32(&Vd[r * VSTR + ld4]),
                      &V[(size_t)((b * Sq + k0 + r) * Dm) + h * 64 + ld4]);
        }
    };

    #pragma unroll
    for (int i = 0; i < 8; i++) {
        int r = lr + i * 8;
        cpasync16(smem_u32(&Qs[r * QSTR + ld4]),
                  &Q[(size_t)((b * Sq + q0 + r) * Dm) + h * 64 + ld4]);
    }
    loadKV(Ks0, Vs0, 0);
    cp_commit();

    const int nkt = causal ? (blockIdx.x + 1) : (Sq / 64);
    cp_wait<0>();
    __syncthreads();

    // pre-split Q fragments: 4 k16-steps x 4 regs (loop-invariant)
    uint32_t qh[4][4], ql[4][4];
    #pragma unroll
    for (int ks = 0; ks < 4; ks++) {
        const float* ab = &Qs[wq * QSTR + ks * 16];
        float2 p0 = *(const float2*)&ab[g * QSTR + 2 * tg];
        float2 p1 = *(const float2*)&ab[(g + 8) * QSTR + 2 * tg];
        float2 p2 = *(const float2*)&ab[g * QSTR + 2 * tg + 8];
        float2 p3 = *(const float2*)&ab[(g + 8) * QSTR + 2 * tg + 8];
        pack2(p0.x, p0.y, qh[ks][0], ql[ks][0]);
        pack2(p1.x, p1.y, qh[ks][1], ql[ks][1]);
        pack2(p2.x, p2.y, qh[ks][2], ql[ks][2]);
        pack2(p3.x, p3.y, qh[ks][3], ql[ks][3]);
    }

    if (nkt > 1) { loadKV(Ks1, Vs1, 64); cp_commit(); }

    float o[8][4] = {};
    float m0p = -1e30f, m1p = -1e30f, l0 = 0.f, l1 = 0.f;

    for (int kt = 0; kt < nkt; kt++) {
        float* Kc = (kt & 1) ? Ks1 : Ks0;
        float* Vc = (kt & 1) ? Vs1 : Vs0;
        if (kt > 0) { cp_wait<0>(); __syncthreads(); }
        if (kt + 1 < nkt) {
            loadKV((kt & 1) ? Ks0 : Ks1, (kt & 1) ? Vs0 : Vs1, (kt + 1) * 64);
            cp_commit();
        }
        // ---- S = Q . K^T (Ks rows are keys: B^T layout, float2 frags) ----
        float s[8][4] = {};
        #pragma unroll
        for (int ks = 0; ks < 4; ks++) {
            const int kk = ks * 16;
            #pragma unroll
            for (int nt = 0; nt < 8; nt++) {
                const float* bb = &Kc[(nt * 8 + g) * QSTR + kk];
                float2 p0 = *(const float2*)&bb[2 * tg];
                float2 p1 = *(const float2*)&bb[2 * tg + 8];
                uint32_t bhf[2], blf[2];
                pack2(p0.x, p0.y, bhf[0], blf[0]);
                pack2(p1.x, p1.y, bhf[1], blf[1]);
                mma3(s[nt], qh[ks], ql[ks], bhf, blf);
            }
        }
        // ---- scale + diagonal-tile causal mask ----
        const bool diag = causal && (kt == blockIdx.x);
        #pragma unroll
        for (int nt = 0; nt < 8; nt++) {
            s[nt][0] *= 0.125f; s[nt][1] *= 0.125f;
            s[nt][2] *= 0.125f; s[nt][3] *= 0.125f;
            if (diag) {
                int col = kt * 64 + nt * 8 + tg * 2;
                int r0 = q0 + wq + g, r1 = r0 + 8;
                if (col     > r0) s[nt][0] = NEGV;
                if (col + 1 > r0) s[nt][1] = NEGV;
                if (col     > r1) s[nt][2] = NEGV;
                if (col + 1 > r1) s[nt][3] = NEGV;
            }
        }
        // ---- online softmax ----
        float m0 = -1e30f, m1 = -1e30f;
        #pragma unroll
        for (int nt = 0; nt < 8; nt++) {
            m0 = fmaxf(m0, fmaxf(s[nt][0], s[nt][1]));
            m1 = fmaxf(m1, fmaxf(s[nt][2], s[nt][3]));
        }
        m0 = fmaxf(m0, __shfl_xor_sync(0xffffffffu, m0, 1));
        m0 = fmaxf(m0, __shfl_xor_sync(0xffffffffu, m0, 2));
        m1 = fmaxf(m1, __shfl_xor_sync(0xffffffffu, m1, 1));
        m1 = fmaxf(m1, __shfl_xor_sync(0xffffffffu, m1, 2));
        float mn0 = fmaxf(m0p, m0), mn1 = fmaxf(m1p, m1);
        float a0 = __expf(m0p - mn0), a1 = __expf(m1p - mn1);
        m0p = mn0; m1p = mn1;

        float rs0 = 0.f, rs1 = 0.f;
        #pragma unroll
        for (int nt = 0; nt < 8; nt++) {
            float p0 = __expf(s[nt][0] - mn0), p1 = __expf(s[nt][1] - mn0);
            float p2 = __expf(s[nt][2] - mn1), p3 = __expf(s[nt][3] - mn1);
            rs0 += p0 + p1; rs1 += p2 + p3;
            *(float2*)&Ps[(wq + g) * PSTR + nt * 8 + tg * 2]     = make_float2(p0, p1);
            *(float2*)&Ps[(wq + g + 8) * PSTR + nt * 8 + tg * 2] = make_float2(p2, p3);
        }
        rs0 += __shfl_xor_sync(0xffffffffu, rs0, 1);
        rs0 += __shfl_xor_sync(0xffffffffu, rs0, 2);
        rs1 += __shfl_xor_sync(0xffffffffu, rs1, 1);
        rs1 += __shfl_xor_sync(0xffffffffu, rs1, 2);
        l0 = l0 * a0 + rs0;
        l1 = l1 * a1 + rs1;
        #pragma unroll
        for (int nt = 0; nt < 8; nt++) {
            o[nt][0] *= a0; o[nt][1] *= a0;
            o[nt][2] *= a1; o[nt][3] *= a1;
        }
        __syncwarp();   // Ps rows are warp-private
        // ---- O += P . V  (P: A-operand float2 frags; V: [k][n], scalar-pair frags) ----
        #pragma unroll
        for (int ks = 0; ks < 4; ks++) {
            const int kk = ks * 16;
            uint32_t ah[4], al[4];
            const float* ab = &Ps[wq * PSTR + kk];
            float2 p0 = *(const float2*)&ab[g * PSTR + 2 * tg];
            float2 p1 = *(const float2*)&ab[(g + 8) * PSTR + 2 * tg];
            float2 p2 = *(const float2*)&ab[g * PSTR + 2 * tg + 8];
            float2 p3 = *(const float2*)&ab[(g + 8) * PSTR + 2 * tg + 8];
            pack2(p0.x, p0.y, ah[0], al[0]);
            pack2(p1.x, p1.y, ah[1], al[1]);
            pack2(p2.x, p2.y, ah[2], al[2]);
            pack2(p3.x, p3.y, ah[3], al[3]);
            #pragma unroll
            for (int nt = 0; nt < 8; nt++) {
                const float* bb = &Vc[nt * 8 + g];
                float f0 = bb[(kk + 2 * tg) * VSTR],     f1 = bb[(kk + 2 * tg + 1) * VSTR];
                float f2 = bb[(kk + 2 * tg + 8) * VSTR], f3 = bb[(kk + 2 * tg + 9) * VSTR];
                uint32_t bhf[2], blf[2];
                pack2(f0, f1, bhf[0], blf[0]);
                pack2(f2, f3, bhf[1], blf[1]);
                mma3(o[nt], ah, al, bhf, blf);
            }
        }
        __syncwarp();
    }
    // ---- epilogue ----
    float inv0 = 1.0f / l0, inv1 = 1.0f / l1;
    #pragma unroll
    for (int nt = 0; nt < 8; nt++) {
        int col = h * 64 + nt * 8 + tg * 2;
        size_t r0 = (size_t)(b * Sq + q0 + wq + g);
        *(float2*)&O[r0 * Dm + col] = make_float2(o[nt][0] * inv0, o[nt][1] * inv0);
        *(float2*)&O[(r0 + 8) * Dm + col] = make_float2(o[nt][2] * inv1, o[nt][3] * inv1);
    }
}

// ---------------- out = LayerNorm(X + R) ----------------
__global__ void add_ln_kernel(const float* __restrict__ X, const float* __restrict__ R,
                              float* __restrict__ O) {
    const int row = blockIdx.x;
    const int t = threadIdx.x;
    const float* x = X + (size_t)row * Dm;
    const float* r = R + (size_t)row * Dm;
    float v0 = x[t] + r[t], v1 = x[t + 256] + r[t + 256];
    __shared__ float red[256];
    red[t] = v0 + v1; __syncthreads();
    for (int s = 128; s > 0; s >>= 1) { if (t < s) red[t] += red[t + s]; __syncthreads(); }
    float mean = red[0] * (1.0f / Dm); __syncthreads();
    float d0 = v0 - mean, d1 = v1 - mean;
    red[t] = d0 * d0 + d1 * d1; __syncthreads();
    for (int s = 128; s > 0; s >>= 1) { if (t < s) red[t] += red[t + s]; __syncthreads(); }
    float inv = rsqrtf(red[0] * (1.0f / Dm) + 1e-5f);
    float* o = O + (size_t)row * Dm;
    o[t] = d0 * inv; o[t + 256] = d1 * inv;
}

// ---------------- host orchestration ----------------
struct Bufs { float *Q, *K, *V, *Ctx, *Tmp, *Ffn, *Enc, *Dec; };

static void attn_block(const float* xq, const float* xkv,
                       const float* Wq, const float* Wk, const float* Wv, const float* Wo,
                       int causal, float* dst, const Bufs& bf) {
    dim3 gP(TOK / BM, Dm / BN);
    gemm_bf16<false><<<gP, 128>>>(xq,  Wq, bf.Q, TOK, Dm, Dm);
    gemm_bf16<false><<<gP, 128>>>(xkv, Wk, bf.K, TOK, Dm, Dm);
    gemm_bf16<false><<<gP, 128>>>(xkv, Wv, bf.V, TOK, Dm, Dm);
    flash_bf16<<<dim3(Sq / 64, Bz * Hh), 128, SMFL>>>(bf.Q, bf.K, bf.V, bf.Ctx, causal);
    gemm_bf16<false><<<gP, 128>>>(bf.Ctx, Wo, bf.Tmp, TOK, Dm, Dm);
    add_ln_kernel<<<TOK, 256>>>(bf.Tmp, xq, dst);
}

static void ffn_block(const float* x, const float* W1, const float* W2,
                      float* dst, const Bufs& bf) {
    gemm_bf16<true ><<<dim3(TOK / BM, FF / BN), 128>>>(x, W1, bf.Ffn, TOK, FF, Dm);
    gemm_bf16<false><<<dim3(TOK / BM, Dm / BN), 128>>>(bf.Ffn, W2, bf.Tmp, TOK, Dm, FF);
    add_ln_kernel<<<TOK, 256>>>(bf.Tmp, x, dst);
}

extern "C" void kernel_launch(void* const* d_in, const int* in_sizes, int n_in,
                              void* d_out, int out_size) {
    const float* enc_in  = (const float*)d_in[0];
    const float* dec_in  = (const float*)d_in[1];
    // d_in[2] (dec_self_attn_mask) is exactly tril(ones) -> causal flag
    const float* enc_Wq  = (const float*)d_in[3];
    const float* enc_Wk  = (const float*)d_in[4];
    const float* enc_Wv  = (const float*)d_in[5];
    const float* enc_Wo  = (const float*)d_in[6];
    const float* enc_W1  = (const float*)d_in[7];
    const float* enc_W2  = (const float*)d_in[8];
    const float* sa_Wq   = (const float*)d_in[9];
    const float* sa_Wk   = (const float*)d_in[10];
    const float* sa_Wv   = (const float*)d_in[11];
    const float* sa_Wo   = (const float*)d_in[12];
    const float* ca_Wq   = (const float*)d_in[13];
    const float* ca_Wk   = (const float*)d_in[14];
    const float* ca_Wv   = (const float*)d_in[15];
    const float* ca_Wo   = (const float*)d_in[16];
    const float* dec_W1  = (const float*)d_in[17];
    const float* dec_W2  = (const float*)d_in[18];

    cudaFuncSetAttribute(flash_bf16, cudaFuncAttributeMaxDynamicSharedMemorySize, SMFL);

    Bufs bf;
    cudaGetSymbolAddress((void**)&bf.Q,   g_Q);
    cudaGetSymbolAddress((void**)&bf.K,   g_K);
    cudaGetSymbolAddress((void**)&bf.V,   g_V);
    cudaGetSymbolAddress((void**)&bf.Ctx, g_Ctx);
    cudaGetSymbolAddress((void**)&bf.Tmp, g_Tmp);
    cudaGetSymbolAddress((void**)&bf.Ffn, g_Ffn);
    cudaGetSymbolAddress((void**)&bf.Enc, g_Enc);
    cudaGetSymbolAddress((void**)&bf.Dec, g_Dec);

    const size_t WP  = (size_t)Dm * Dm;
    const size_t W1S = (size_t)Dm * FF;
    const size_t W2S = (size_t)FF * Dm;

    // ---- encoder stack ----
    const float* src = enc_in;
    for (int i = 0; i < NL; i++) {
        attn_block(src, src, enc_Wq + i * WP, enc_Wk + i * WP, enc_Wv + i * WP,
                   enc_Wo + i * WP, 0, bf.Enc, bf);
        ffn_block(bf.Enc, enc_W1 + i * W1S, enc_W2 + i * W2S, bf.Enc, bf);
        src = bf.Enc;
    }

    // ---- decoder stack ----
    const float* dsrc = dec_in;
    for (int i = 0; i < NL; i++) {
        attn_block(dsrc, dsrc, sa_Wq + i * WP, sa_Wk + i * WP, sa_Wv + i * WP,
                   sa_Wo + i * WP, 1, bf.Dec, bf);
        attn_block(bf.Dec, bf.Enc, ca_Wq + i * WP, ca_Wk + i * WP, ca_Wv + i * WP,
                   ca_Wo + i * WP, 0, bf.Dec, bf);
        float* out = (i == NL - 1) ? (float*)d_out : bf.Dec;
        ffn_block(bf.Dec, dec_W1 + i * W1S, dec_W2 + i * W2S, out, bf);
        dsrc = bf.Dec;
    }
}